// round 16
// baseline (speedup 1.0000x reference)
#include <cuda_runtime.h>
#include <cuda_fp16.h>
#include <cstdint>

#define NN 2048
#define DD 128
#define HH 40

// Scratch (static __device__ arrays per harness rules)
__device__ __align__(16) __half g_Qh [HH * NN * DD];   // per-head Q*scale (fp16)
__device__ __align__(16) __half g_XVt[HH * NN * DD];   // per-head XV^T (fp16, [d][m])
__device__ __align__(16) __half g_Oh [HH * NN * DD];   // per-head attention output (fp16)
__device__ __align__(16) __half g_Xh [NN * DD];        // fp16 X (keys / A operand)
__device__ __align__(16) __half g_Wth[2 * HH * DD * DD]; // W^T,V^T fp16 [z*40+h][n][k]
__device__ float g_cs  [HH * DD];
__device__ float g_xsp [128 * DD];
__device__ float g_xsum[DD];
__device__ unsigned g_ticket;

// ===========================================================================
// helpers
// ===========================================================================
__device__ __forceinline__ uint32_t s2u(const void* p) {
    uint32_t a;
    asm("{ .reg .u64 t; cvta.to.shared.u64 t, %1; cvt.u32.u64 %0, t; }"
        : "=r"(a) : "l"(p));
    return a;
}
__device__ __forceinline__ void cpasync16(uint32_t s, const void* g) {
    asm volatile("cp.async.cg.shared.global [%0], [%1], 16;" :: "r"(s), "l"(g));
}
__device__ __forceinline__ void cp_commit() {
    asm volatile("cp.async.commit_group;" ::: "memory");
}
__device__ __forceinline__ void cp_wait0() {
    asm volatile("cp.async.wait_group 0;" ::: "memory");
}
__device__ __forceinline__ void cp_wait1() {
    asm volatile("cp.async.wait_group 1;" ::: "memory");
}
// fp32-accum MMA (PV, projections)
__device__ __forceinline__ void mma16816(float (&c)[4], const unsigned (&a)[4],
                                         unsigned b0, unsigned b1) {
    asm volatile(
        "mma.sync.aligned.m16n8k16.row.col.f32.f16.f16.f32 "
        "{%0,%1,%2,%3}, {%4,%5,%6,%7}, {%8,%9}, {%0,%1,%2,%3};\n"
        : "+f"(c[0]), "+f"(c[1]), "+f"(c[2]), "+f"(c[3])
        : "r"(a[0]), "r"(a[1]), "r"(a[2]), "r"(a[3]), "r"(b0), "r"(b1));
}
// f16-accum MMA (QK scores; |S*scale| < 1, precision safe)
__device__ __forceinline__ void mma16816h(unsigned (&c)[2], const unsigned (&a)[4],
                                          unsigned b0, unsigned b1) {
    asm volatile(
        "mma.sync.aligned.m16n8k16.row.col.f16.f16.f16.f16 "
        "{%0,%1}, {%2,%3,%4,%5}, {%6,%7}, {%0,%1};\n"
        : "+r"(c[0]), "+r"(c[1])
        : "r"(a[0]), "r"(a[1]), "r"(a[2]), "r"(a[3]), "r"(b0), "r"(b1));
}
__device__ __forceinline__ float ex2f(float x) {
    float r; asm("ex2.approx.f32 %0, %1;" : "=f"(r) : "f"(x)); return r;
}
__device__ __forceinline__ unsigned packh2(float lo, float hi) {
    unsigned r;
    asm("cvt.rn.f16x2.f32 %0, %1, %2;" : "=r"(r) : "f"(hi), "f"(lo));
    return r;
}

// ---------------------------------------------------------------------------
__global__ void reset_ticket_kernel() { g_ticket = 0u; }

// ---------------------------------------------------------------------------
// Fused prep: blocks [0,1024) X->fp16; [1024,2304) W/V transpose+fp16;
// [2304,2432) X column partial sums (128 partials, 16 rows each).
// ---------------------------------------------------------------------------
__global__ __launch_bounds__(256) void prep_kernel(const float* __restrict__ X,
                                                   const float* __restrict__ W,
                                                   const float* __restrict__ V) {
    __shared__ float tile[32][33];
    int b = blockIdx.x, tid = threadIdx.x;
    if (b < 1024) {
        int i = b * 256 + tid;
        g_Xh[i] = __float2half_rn(X[i]);
    } else if (b < 2304) {
        int b2 = b - 1024;
        int mat = b2 >> 4;
        int rem = b2 & 15;
        int k0 = (rem & 3) * 32, n0 = (rem >> 2) * 32;
        const float* src = (mat < HH ? W + (size_t)mat * DD * DD
                                     : V + (size_t)(mat - HH) * DD * DD);
        int tx = tid & 31, ty = tid >> 5;
        #pragma unroll
        for (int i = 0; i < 4; i++)
            tile[ty + 8 * i][tx] = src[(size_t)(k0 + ty + 8 * i) * DD + n0 + tx];
        __syncthreads();
        __half* dst = g_Wth + (size_t)mat * DD * DD;
        #pragma unroll
        for (int i = 0; i < 4; i++)
            dst[(size_t)(n0 + ty + 8 * i) * DD + k0 + tx] =
                __float2half_rn(tile[tx][ty + 8 * i]);
    } else {
        int p = b - 2304;   // 0..127
        if (tid < 128) {
            const float* ptr = X + (size_t)p * 16 * DD + tid;
            float s = 0.f;
            #pragma unroll
            for (int m = 0; m < 16; m++) s += ptr[m * DD];
            g_xsp[p * DD + tid] = s;
        }
    }
}

__global__ void xsum2_kernel() {
    int c = threadIdx.x;
    float s = 0.f;
    #pragma unroll 8
    for (int p = 0; p < 128; p++) s += g_xsp[p * DD + c];
    g_xsum[c] = s;
}
// colsum[h][e] = sum_k xsum[k] * V[h][k][e]   (exact rank-1 identity)
__global__ void colsum_kernel(const float* __restrict__ V) {
    int h = blockIdx.x, e = threadIdx.x;
    const float* Vh = V + (size_t)h * DD * DD;
    float s = 0.f;
    #pragma unroll 4
    for (int k = 0; k < DD; k++) s += g_xsum[k] * Vh[k * DD + e];
    g_cs[h * DD + e] = s;
}

// ---------------------------------------------------------------------------
// HMMA projections: grid (16, 40, 2). z=0: Q = (X@W)*cs2 -> g_Qh (scale folded)
// z=1: XV = X@V -> g_XVt (transposed via smem staging). 8 warps x 16 rows.
// ---------------------------------------------------------------------------
#define PC_SA 0
#define PC_SB 34816
#define PC_TOTAL 69632

__global__ __launch_bounds__(256, 2) void precompute_mma() {
    extern __shared__ char sm[];
    uint32_t sb = s2u(sm);
    int tid = threadIdx.x;
    int wid = tid >> 5, lane = tid & 31;
    int g = lane >> 2, tau = lane & 3;
    int rb = blockIdx.x, h = blockIdx.y, z = blockIdx.z;

    const uint4* Ag = (const uint4*)g_Xh + (size_t)rb * 2048;
    const uint4* Bg = (const uint4*)g_Wth + ((size_t)z * HH + h) * 2048;
    #pragma unroll
    for (int j = 0; j < 8; j++) {
        int u = tid + j * 256;
        uint32_t so = (u >> 4) * 272 + (u & 15) * 16;
        cpasync16(sb + PC_SA + so, Ag + u);
        cpasync16(sb + PC_SB + so, Bg + u);
    }
    cp_commit();
    cp_wait0();
    __syncthreads();

    const __half* sA = (const __half*)(sm + PC_SA);
    const __half* sB = (const __half*)(sm + PC_SB);
    int r0 = wid * 16 + g;

    unsigned qa[8][4];
    #pragma unroll
    for (int kf = 0; kf < 8; kf++) {
        int k0 = kf * 16 + 2 * tau;
        qa[kf][0] = *(const unsigned*)&sA[r0 * 136 + k0];
        qa[kf][1] = *(const unsigned*)&sA[(r0 + 8) * 136 + k0];
        qa[kf][2] = *(const unsigned*)&sA[r0 * 136 + k0 + 8];
        qa[kf][3] = *(const unsigned*)&sA[(r0 + 8) * 136 + k0 + 8];
    }

    float oc[16][4];
    #pragma unroll
    for (int j = 0; j < 16; j++)
        #pragma unroll
        for (int c = 0; c < 4; c++) oc[j][c] = 0.f;

    #pragma unroll
    for (int kf = 0; kf < 8; kf++) {
        int k0 = kf * 16 + 2 * tau;
        #pragma unroll
        for (int j = 0; j < 16; j++) {
            int n = j * 8 + g;
            unsigned b0 = *(const unsigned*)&sB[n * 136 + k0];
            unsigned b1 = *(const unsigned*)&sB[n * 136 + k0 + 8];
            mma16816(oc[j], qa[kf], b0, b1);
        }
    }

    __syncthreads();   // all warps done with sA/sB before staging reuse
    __half* sT = (__half*)(sm + PC_SA);   // 128 x 136 halfs staging

    if (z == 0) {
        const float cs2 = 0.12751879523595787f;  // (1/sqrt(128)) * log2(e)
        #pragma unroll
        for (int j = 0; j < 16; j++) {
            int c = j * 8 + 2 * tau;
            *(unsigned*)&sT[r0 * 136 + c] =
                packh2(oc[j][0] * cs2, oc[j][1] * cs2);
            *(unsigned*)&sT[(r0 + 8) * 136 + c] =
                packh2(oc[j][2] * cs2, oc[j][3] * cs2);
        }
        __syncthreads();
        uint4* dst = (uint4*)g_Qh + (size_t)h * 32768 + (size_t)rb * 2048;
        #pragma unroll
        for (int q = 0; q < 8; q++) {
            int u = tid + q * 256;
            dst[u] = *(const uint4*)&sT[(u >> 4) * 136 + (u & 15) * 8];
        }
    } else {
        #pragma unroll
        for (int j = 0; j < 16; j++) {
            int d = j * 8 + 2 * tau;
            sT[d * 136 + r0]           = __float2half_rn(oc[j][0]);
            sT[(d + 1) * 136 + r0]     = __float2half_rn(oc[j][1]);
            sT[d * 136 + r0 + 8]       = __float2half_rn(oc[j][2]);
            sT[(d + 1) * 136 + r0 + 8] = __float2half_rn(oc[j][3]);
        }
        __syncthreads();
        uint4* dst = (uint4*)g_XVt + (size_t)h * 32768;
        #pragma unroll
        for (int q = 0; q < 8; q++) {
            int u = tid + q * 256;
            int d = u >> 4, c8 = u & 15;
            dst[d * 256 + rb * 16 + c8] = *(const uint4*)&sT[d * 136 + c8 * 8];
        }
    }
}

// ---------------------------------------------------------------------------
// Persistent HMMA flash attention. M_warp = 32 (2x B-fragment reuse).
// 304 CTAs x 128 threads (4 warps x 32 query rows = 128-row items),
// 64-key tiles, 2 CTAs/SM.  Items: 640 = 40 heads x 16 row-blocks.
// SMEM: CS + Q(128x136h) + K x2 (64x136h) + VT x2 (128x72h) = 107 KB.
// ---------------------------------------------------------------------------
#define AT_CS   0
#define AT_Q    512
#define AT_K0   35328
#define AT_K1   52736
#define AT_V0   70144
#define AT_V1   88576
#define AT_TOTAL 107008
#define N_ITEMS (16 * HH)

__global__ __launch_bounds__(128, 2) void attn_kernel() {
    extern __shared__ char sm[];
    uint32_t sb = s2u(sm);
    __shared__ unsigned s_item;
    int tid = threadIdx.x;
    int wid = tid >> 5, lane = tid & 31;
    int g = lane >> 2, tau = lane & 3;

    for (;;) {
        if (tid == 0) s_item = atomicAdd(&g_ticket, 1u);
        __syncthreads();
        unsigned item = s_item;
        if (item >= N_ITEMS) break;
        int h = (int)(item >> 4);
        int rb = (int)(item & 15u);

        const size_t hbase = (size_t)h * NN * DD;
        const uint4* Qg = (const uint4*)(g_Qh + hbase + (size_t)rb * 128 * DD);
        const uint4* Kg = (const uint4*)g_Xh;
        const uint4* Vt = (const uint4*)(g_XVt + hbase);

        ((float*)(sm + AT_CS))[tid] = g_cs[h * DD + tid];

        // ---- prologue: Q (128x128) + K0 (64x128) + VT0 (128x64) ----
        #pragma unroll
        for (int j = 0; j < 16; j++) {
            int u = tid + j * 128;      // 2048 uint4
            cpasync16(sb + AT_Q + (u >> 4) * 272 + (u & 15) * 16, Qg + u);
        }
        #pragma unroll
        for (int j = 0; j < 8; j++) {
            int u = tid + j * 128;      // 1024 uint4 each
            cpasync16(sb + AT_K0 + (u >> 4) * 272 + (u & 15) * 16, Kg + u);
            cpasync16(sb + AT_V0 + (u >> 3) * 144 + (u & 7) * 16,
                      Vt + (u >> 3) * 256 + (u & 7));
        }
        cp_commit();

        const __half* sQ = (const __half*)(sm + AT_Q);

        float oc[2][16][4];
        #pragma unroll
        for (int mi = 0; mi < 2; mi++)
            #pragma unroll
            for (int j = 0; j < 16; j++)
                #pragma unroll
                for (int c = 0; c < 4; c++) oc[mi][j][c] = 0.f;
        float dm[2][2] = {{0.f, 0.f}, {0.f, 0.f}};

        for (int t = 0; t < 32; t++) {
            // WAR guard: prefetch below overwrites the t-1 buffer.
            __syncthreads();

            if (t + 1 < 32) {
                uint32_t kb = sb + (((t + 1) & 1) ? AT_K1 : AT_K0);
                uint32_t vb = sb + (((t + 1) & 1) ? AT_V1 : AT_V0);
                const uint4* Kt = Kg + (t + 1) * 1024;
                #pragma unroll
                for (int j = 0; j < 8; j++) {
                    int u = tid + j * 128;
                    cpasync16(kb + (u >> 4) * 272 + (u & 15) * 16, Kt + u);
                    cpasync16(vb + (u >> 3) * 144 + (u & 7) * 16,
                              Vt + (u >> 3) * 256 + (t + 1) * 8 + (u & 7));
                }
                cp_commit();
                cp_wait1();   // tile t's group (prologue incl. Q at t=0) done
            } else {
                cp_wait0();
            }
            __syncthreads();

            const __half* sK = (const __half*)(sm + ((t & 1) ? AT_K1 : AT_K0));
            const __half* sV = (const __half*)(sm + ((t & 1) ? AT_V1 : AT_V0));

            // ---- QK (f16 accum): warp tile 32 rows x 64 keys, k = 128 ----
            unsigned sc[2][8][2];
            #pragma unroll
            for (int mi = 0; mi < 2; mi++)
                #pragma unroll
                for (int j = 0; j < 8; j++) { sc[mi][j][0] = 0u; sc[mi][j][1] = 0u; }

            #pragma unroll
            for (int kf = 0; kf < 8; kf++) {
                int k0 = kf * 16 + 2 * tau;
                unsigned a[2][4];
                #pragma unroll
                for (int mi = 0; mi < 2; mi++) {
                    int row = wid * 32 + mi * 16 + g;
                    a[mi][0] = *(const unsigned*)&sQ[row * 136 + k0];
                    a[mi][1] = *(const unsigned*)&sQ[(row + 8) * 136 + k0];
                    a[mi][2] = *(const unsigned*)&sQ[row * 136 + k0 + 8];
                    a[mi][3] = *(const unsigned*)&sQ[(row + 8) * 136 + k0 + 8];
                }
                #pragma unroll
                for (int j = 0; j < 8; j++) {
                    int n = j * 8 + g;
                    unsigned b0 = *(const unsigned*)&sK[n * 136 + k0];
                    unsigned b1 = *(const unsigned*)&sK[n * 136 + k0 + 8];
                    mma16816h(sc[0][j], a[0], b0, b1);
                    mma16816h(sc[1][j], a[1], b0, b1);
                }
            }

            // ---- exp + PV interleaved per 16-key chunk ----
            #pragma unroll
            for (int jj = 0; jj < 4; jj++) {
                unsigned pa[2][4];
                #pragma unroll
                for (int jh = 0; jh < 2; jh++) {
                    int j = jj * 2 + jh;
                    #pragma unroll
                    for (int mi = 0; mi < 2; mi++) {
                        float2 lo = __half22float2(*(const __half2*)&sc[mi][j][0]);
                        float2 hi = __half22float2(*(const __half2*)&sc[mi][j][1]);
                        float e0 = ex2f(lo.x);
                        float e1 = ex2f(lo.y);
                        float e2 = ex2f(hi.x);
                        float e3 = ex2f(hi.y);
                        dm[mi][0] += e0 + e1;
                        dm[mi][1] += e2 + e3;
                        pa[mi][jh * 2]     = packh2(e0 - 1.f, e1 - 1.f);
                        pa[mi][jh * 2 + 1] = packh2(e2 - 1.f, e3 - 1.f);
                    }
                }
                int k0 = jj * 16 + 2 * tau;
                #pragma unroll
                for (int j = 0; j < 16; j++) {
                    int n = j * 8 + g;
                    unsigned b0 = *(const unsigned*)&sV[n * 72 + k0];
                    unsigned b1 = *(const unsigned*)&sV[n * 72 + k0 + 8];
                    mma16816(oc[0][j], pa[0], b0, b1);
                    mma16816(oc[1][j], pa[1], b0, b1);
                }
            }
        }

        // ---- denominator quad-reduction (deterministic) ----
        #pragma unroll
        for (int mi = 0; mi < 2; mi++)
            #pragma unroll
            for (int hh = 0; hh < 2; hh++) {
                dm[mi][hh] += __shfl_xor_sync(0xffffffffu, dm[mi][hh], 1);
                dm[mi][hh] += __shfl_xor_sync(0xffffffffu, dm[mi][hh], 2);
            }

        // ---- epilogue: (p'V + colsum) / denom -> g_Oh (fp16) ----
        const float* cs = (const float*)(sm + AT_CS);
        __half* Og = g_Oh + hbase + (size_t)rb * 128 * DD;
        #pragma unroll
        for (int mi = 0; mi < 2; mi++) {
            int row = wid * 32 + mi * 16 + g;
            float inv0 = 1.f / dm[mi][0];
            float inv1 = 1.f / dm[mi][1];
            #pragma unroll
            for (int j = 0; j < 16; j++) {
                int c = j * 8 + 2 * tau;
                float2 csv = *(const float2*)&cs[c];
                *(unsigned*)&Og[row * DD + c] =
                    packh2((oc[mi][j][0] + csv.x) * inv0,
                           (oc[mi][j][1] + csv.y) * inv0);
                *(unsigned*)&Og[(row + 8) * DD + c] =
                    packh2((oc[mi][j][2] + csv.x) * inv1,
                           (oc[mi][j][3] + csv.y) * inv1);
            }
        }

        // separate this item's smem reads from next item's writes
        __syncthreads();
    }
}

// ---------------------------------------------------------------------------
// Sum over heads (fp16 O) + 1e-8 * colsum correction -> d_out
// ---------------------------------------------------------------------------
__global__ void reduce_kernel(float* __restrict__ out) {
    int i4 = blockIdx.x * 256 + threadIdx.x;
    int base = i4 * 4;
    int c4 = base & 127;
    float4 s = make_float4(0.f, 0.f, 0.f, 0.f);
    #pragma unroll 4
    for (int h = 0; h < HH; h++) {
        const __half2* oh = (const __half2*)&g_Oh[(size_t)h * NN * DD + base];
        float2 a = __half22float2(oh[0]);
        float2 b = __half22float2(oh[1]);
        const float* cs = &g_cs[h * DD + c4];
        s.x += a.x + 1e-8f * cs[0];
        s.y += a.y + 1e-8f * cs[1];
        s.z += b.x + 1e-8f * cs[2];
        s.w += b.y + 1e-8f * cs[3];
    }
    *(float4*)&out[base] = s;
}

// ---------------------------------------------------------------------------
extern "C" void kernel_launch(void* const* d_in, const int* in_sizes, int n_in,
                              void* d_out, int out_size) {
    const float* X = (const float*)d_in[0];
    const float* W = (const float*)d_in[1];
    const float* V = (const float*)d_in[2];
    float* out = (float*)d_out;

    reset_ticket_kernel<<<1, 1>>>();
    prep_kernel<<<2432, 256>>>(X, W, V);
    xsum2_kernel<<<1, 128>>>();
    colsum_kernel<<<HH, 128>>>(V);

    cudaFuncSetAttribute(precompute_mma,
                         cudaFuncAttributeMaxDynamicSharedMemorySize, PC_TOTAL);
    precompute_mma<<<dim3(16, HH, 2), 256, PC_TOTAL>>>();

    cudaFuncSetAttribute(attn_kernel, cudaFuncAttributeMaxDynamicSharedMemorySize,
                         AT_TOTAL);
    attn_kernel<<<304, 128, AT_TOTAL>>>();

    reduce_kernel<<<(NN * DD) / 1024, 256>>>(out);
}

// round 17
// speedup vs baseline: 1.1594x; 1.1594x over previous
#include <cuda_runtime.h>
#include <cuda_fp16.h>
#include <cstdint>

#define NN 2048
#define DD 128
#define HH 40

// Scratch (static __device__ arrays per harness rules)
__device__ __align__(16) __half g_Qh [HH * NN * DD];   // per-head Q*scale (fp16)
__device__ __align__(16) __half g_XVt[HH * NN * DD];   // per-head XV^T (fp16, [d][m])
__device__ __align__(16) __half g_Oh [HH * NN * DD];   // per-head attention output (fp16)
__device__ __align__(16) __half g_Xh [NN * DD];        // fp16 X (keys / A operand)
__device__ __align__(16) __half g_Wth[2 * HH * DD * DD]; // W^T,V^T fp16 [z*40+h][n][k]
__device__ float g_cs  [HH * DD];
__device__ float g_xsp [128 * DD];

// ===========================================================================
// helpers
// ===========================================================================
__device__ __forceinline__ uint32_t s2u(const void* p) {
    uint32_t a;
    asm("{ .reg .u64 t; cvta.to.shared.u64 t, %1; cvt.u32.u64 %0, t; }"
        : "=r"(a) : "l"(p));
    return a;
}
__device__ __forceinline__ void cpasync16(uint32_t s, const void* g) {
    asm volatile("cp.async.cg.shared.global [%0], [%1], 16;" :: "r"(s), "l"(g));
}
__device__ __forceinline__ void cp_commit() {
    asm volatile("cp.async.commit_group;" ::: "memory");
}
__device__ __forceinline__ void cp_wait0() {
    asm volatile("cp.async.wait_group 0;" ::: "memory");
}
__device__ __forceinline__ void cp_wait1() {
    asm volatile("cp.async.wait_group 1;" ::: "memory");
}
// fp32-accum MMA (PV, projections)
__device__ __forceinline__ void mma16816(float (&c)[4], const unsigned (&a)[4],
                                         unsigned b0, unsigned b1) {
    asm volatile(
        "mma.sync.aligned.m16n8k16.row.col.f32.f16.f16.f32 "
        "{%0,%1,%2,%3}, {%4,%5,%6,%7}, {%8,%9}, {%0,%1,%2,%3};\n"
        : "+f"(c[0]), "+f"(c[1]), "+f"(c[2]), "+f"(c[3])
        : "r"(a[0]), "r"(a[1]), "r"(a[2]), "r"(a[3]), "r"(b0), "r"(b1));
}
// f16-accum MMA (QK scores; |S*scale| < 1, precision safe)
__device__ __forceinline__ void mma16816h(unsigned (&c)[2], const unsigned (&a)[4],
                                          unsigned b0, unsigned b1) {
    asm volatile(
        "mma.sync.aligned.m16n8k16.row.col.f16.f16.f16.f16 "
        "{%0,%1}, {%2,%3,%4,%5}, {%6,%7}, {%0,%1};\n"
        : "+r"(c[0]), "+r"(c[1])
        : "r"(a[0]), "r"(a[1]), "r"(a[2]), "r"(a[3]), "r"(b0), "r"(b1));
}
__device__ __forceinline__ float ex2f(float x) {
    float r; asm("ex2.approx.f32 %0, %1;" : "=f"(r) : "f"(x)); return r;
}
__device__ __forceinline__ unsigned packh2(float lo, float hi) {
    unsigned r;
    asm("cvt.rn.f16x2.f32 %0, %1, %2;" : "=r"(r) : "f"(hi), "f"(lo));
    return r;
}

// ---------------------------------------------------------------------------
// Fused prep: blocks [0,1024) X->fp16; [1024,2304) W/V transpose+fp16;
// [2304,2432) X column partial sums (128 partials, 16 rows each).
// ---------------------------------------------------------------------------
__global__ __launch_bounds__(256) void prep_kernel(const float* __restrict__ X,
                                                   const float* __restrict__ W,
                                                   const float* __restrict__ V) {
    __shared__ float tile[32][33];
    int b = blockIdx.x, tid = threadIdx.x;
    if (b < 1024) {
        int i = b * 256 + tid;
        g_Xh[i] = __float2half_rn(X[i]);
    } else if (b < 2304) {
        int b2 = b - 1024;
        int mat = b2 >> 4;
        int rem = b2 & 15;
        int k0 = (rem & 3) * 32, n0 = (rem >> 2) * 32;
        const float* src = (mat < HH ? W + (size_t)mat * DD * DD
                                     : V + (size_t)(mat - HH) * DD * DD);
        int tx = tid & 31, ty = tid >> 5;
        #pragma unroll
        for (int i = 0; i < 4; i++)
            tile[ty + 8 * i][tx] = src[(size_t)(k0 + ty + 8 * i) * DD + n0 + tx];
        __syncthreads();
        __half* dst = g_Wth + (size_t)mat * DD * DD;
        #pragma unroll
        for (int i = 0; i < 4; i++)
            dst[(size_t)(n0 + ty + 8 * i) * DD + k0 + tx] =
                __float2half_rn(tile[tx][ty + 8 * i]);
    } else {
        int p = b - 2304;   // 0..127
        if (tid < 128) {
            const float* ptr = X + (size_t)p * 16 * DD + tid;
            float s = 0.f;
            #pragma unroll
            for (int m = 0; m < 16; m++) s += ptr[m * DD];
            g_xsp[p * DD + tid] = s;
        }
    }
}

// ---------------------------------------------------------------------------
// Fused xsum + colsum (rank-1 identity): one 512-thread block per head.
// Stage 1: xsum[c] = sum_p xsp[p][c]  (4-way p-split, fixed-order combine)
// Stage 2: cs[h][e] = sum_k xsum[k] * V[h][k][e]  (4-way k-split, same)
// Deterministic: fixed partial ranges + fixed combine order.
// ---------------------------------------------------------------------------
__global__ __launch_bounds__(512) void colsum_kernel(const float* __restrict__ V) {
    __shared__ float sp[4][128];
    __shared__ float sxs[128];
    int h = blockIdx.x;
    int c = threadIdx.x & 127;
    int q = threadIdx.x >> 7;     // 0..3

    float s = 0.f;
    #pragma unroll 8
    for (int p = q * 32; p < q * 32 + 32; p++) s += g_xsp[p * DD + c];
    sp[q][c] = s;
    __syncthreads();
    if (threadIdx.x < 128)
        sxs[c] = sp[0][c] + sp[1][c] + sp[2][c] + sp[3][c];
    __syncthreads();

    const float* Vh = V + (size_t)h * DD * DD;
    float d = 0.f;
    #pragma unroll 8
    for (int k = q * 32; k < q * 32 + 32; k++) d += sxs[k] * Vh[k * DD + c];
    sp[q][c] = d;
    __syncthreads();
    if (threadIdx.x < 128)
        g_cs[h * DD + c] = sp[0][c] + sp[1][c] + sp[2][c] + sp[3][c];
}

// ---------------------------------------------------------------------------
// HMMA projections: grid (16, 40, 2). z=0: Q = (X@W)*cs2 -> g_Qh (scale folded)
// z=1: XV = X@V -> g_XVt (transposed via smem staging). 8 warps x 16 rows.
// ---------------------------------------------------------------------------
#define PC_SA 0
#define PC_SB 34816
#define PC_TOTAL 69632

__global__ __launch_bounds__(256, 2) void precompute_mma() {
    extern __shared__ char sm[];
    uint32_t sb = s2u(sm);
    int tid = threadIdx.x;
    int wid = tid >> 5, lane = tid & 31;
    int g = lane >> 2, tau = lane & 3;
    int rb = blockIdx.x, h = blockIdx.y, z = blockIdx.z;

    const uint4* Ag = (const uint4*)g_Xh + (size_t)rb * 2048;
    const uint4* Bg = (const uint4*)g_Wth + ((size_t)z * HH + h) * 2048;
    #pragma unroll
    for (int j = 0; j < 8; j++) {
        int u = tid + j * 256;
        uint32_t so = (u >> 4) * 272 + (u & 15) * 16;
        cpasync16(sb + PC_SA + so, Ag + u);
        cpasync16(sb + PC_SB + so, Bg + u);
    }
    cp_commit();
    cp_wait0();
    __syncthreads();

    const __half* sA = (const __half*)(sm + PC_SA);
    const __half* sB = (const __half*)(sm + PC_SB);
    int r0 = wid * 16 + g;

    unsigned qa[8][4];
    #pragma unroll
    for (int kf = 0; kf < 8; kf++) {
        int k0 = kf * 16 + 2 * tau;
        qa[kf][0] = *(const unsigned*)&sA[r0 * 136 + k0];
        qa[kf][1] = *(const unsigned*)&sA[(r0 + 8) * 136 + k0];
        qa[kf][2] = *(const unsigned*)&sA[r0 * 136 + k0 + 8];
        qa[kf][3] = *(const unsigned*)&sA[(r0 + 8) * 136 + k0 + 8];
    }

    float oc[16][4];
    #pragma unroll
    for (int j = 0; j < 16; j++)
        #pragma unroll
        for (int c = 0; c < 4; c++) oc[j][c] = 0.f;

    #pragma unroll
    for (int kf = 0; kf < 8; kf++) {
        int k0 = kf * 16 + 2 * tau;
        #pragma unroll
        for (int j = 0; j < 16; j++) {
            int n = j * 8 + g;
            unsigned b0 = *(const unsigned*)&sB[n * 136 + k0];
            unsigned b1 = *(const unsigned*)&sB[n * 136 + k0 + 8];
            mma16816(oc[j], qa[kf], b0, b1);
        }
    }

    __syncthreads();   // all warps done with sA/sB before staging reuse
    __half* sT = (__half*)(sm + PC_SA);   // 128 x 136 halfs staging

    if (z == 0) {
        const float cs2 = 0.12751879523595787f;  // (1/sqrt(128)) * log2(e)
        #pragma unroll
        for (int j = 0; j < 16; j++) {
            int c = j * 8 + 2 * tau;
            *(unsigned*)&sT[r0 * 136 + c] =
                packh2(oc[j][0] * cs2, oc[j][1] * cs2);
            *(unsigned*)&sT[(r0 + 8) * 136 + c] =
                packh2(oc[j][2] * cs2, oc[j][3] * cs2);
        }
        __syncthreads();
        uint4* dst = (uint4*)g_Qh + (size_t)h * 32768 + (size_t)rb * 2048;
        #pragma unroll
        for (int q = 0; q < 8; q++) {
            int u = tid + q * 256;
            dst[u] = *(const uint4*)&sT[(u >> 4) * 136 + (u & 15) * 8];
        }
    } else {
        #pragma unroll
        for (int j = 0; j < 16; j++) {
            int d = j * 8 + 2 * tau;
            sT[d * 136 + r0]           = __float2half_rn(oc[j][0]);
            sT[(d + 1) * 136 + r0]     = __float2half_rn(oc[j][1]);
            sT[d * 136 + r0 + 8]       = __float2half_rn(oc[j][2]);
            sT[(d + 1) * 136 + r0 + 8] = __float2half_rn(oc[j][3]);
        }
        __syncthreads();
        uint4* dst = (uint4*)g_XVt + (size_t)h * 32768;
        #pragma unroll
        for (int q = 0; q < 8; q++) {
            int u = tid + q * 256;
            int d = u >> 4, c8 = u & 15;
            dst[d * 256 + rb * 16 + c8] = *(const uint4*)&sT[d * 136 + c8 * 8];
        }
    }
}

// ---------------------------------------------------------------------------
// HMMA flash attention (R13 configuration — empirical optimum of this family):
// f16-accum QK (scale pre-folded), fp32-accum PV.
// grid (32, 40), 128 threads (4 warps x 16 query rows), 64-key tiles,
// 2 CTAs/SM, Q in smem -> registers, fp16 O store.
// ---------------------------------------------------------------------------
#define AT_CS   0
#define AT_Q    512
#define AT_K0   18432
#define AT_K1   36352
#define AT_V0   54272
#define AT_V1   72704
#define AT_TOTAL 91136

__global__ __launch_bounds__(128, 2) void attn_kernel() {
    extern __shared__ char sm[];
    uint32_t sb = s2u(sm);
    int tid = threadIdx.x;
    int wid = tid >> 5, lane = tid & 31;
    int g = lane >> 2, tau = lane & 3;
    int rb = blockIdx.x, h = blockIdx.y;

    const size_t hbase = (size_t)h * NN * DD;
    const uint4* Qg = (const uint4*)(g_Qh + hbase + (size_t)rb * 64 * DD);
    const uint4* Kg = (const uint4*)g_Xh;
    const uint4* Vt = (const uint4*)(g_XVt + hbase);

    ((float*)(sm + AT_CS))[tid] = g_cs[h * DD + tid];

    // ---- prologue: Q (64x128) + K0 (64x128) + VT0 (128x64) ----
    #pragma unroll
    for (int j = 0; j < 8; j++) {
        int u = tid + j * 128;
        uint32_t so = (u >> 4) * 272 + (u & 15) * 16;
        cpasync16(sb + AT_Q  + so, Qg + u);
        cpasync16(sb + AT_K0 + so, Kg + u);
        cpasync16(sb + AT_V0 + (u >> 3) * 144 + (u & 7) * 16,
                  Vt + (u >> 3) * 256 + (u & 7));
    }
    cp_commit();
    cp_wait0();
    __syncthreads();

    // ---- Q fragments to registers ----
    const __half* sQ = (const __half*)(sm + AT_Q);
    int r0 = wid * 16 + g;
    unsigned qa[8][4];
    #pragma unroll
    for (int kf = 0; kf < 8; kf++) {
        int k0 = kf * 16 + 2 * tau;
        qa[kf][0] = *(const unsigned*)&sQ[r0 * 136 + k0];
        qa[kf][1] = *(const unsigned*)&sQ[(r0 + 8) * 136 + k0];
        qa[kf][2] = *(const unsigned*)&sQ[r0 * 136 + k0 + 8];
        qa[kf][3] = *(const unsigned*)&sQ[(r0 + 8) * 136 + k0 + 8];
    }

    float oc[16][4];
    #pragma unroll
    for (int j = 0; j < 16; j++)
        #pragma unroll
        for (int c = 0; c < 4; c++) oc[j][c] = 0.f;
    float d0 = 0.f, d1 = 0.f;

    for (int t = 0; t < 32; t++) {
        // WAR guard: the prefetch below overwrites the t-1 buffer.
        __syncthreads();

        if (t + 1 < 32) {
            uint32_t kb = sb + (((t + 1) & 1) ? AT_K1 : AT_K0);
            uint32_t vb = sb + (((t + 1) & 1) ? AT_V1 : AT_V0);
            const uint4* Kt = Kg + (t + 1) * 1024;
            #pragma unroll
            for (int j = 0; j < 8; j++) {
                int u = tid + j * 128;
                cpasync16(kb + (u >> 4) * 272 + (u & 15) * 16, Kt + u);
                cpasync16(vb + (u >> 3) * 144 + (u & 7) * 16,
                          Vt + (u >> 3) * 256 + (t + 1) * 8 + (u & 7));
            }
            cp_commit();
            cp_wait1();   // tile t's group (prologue at t=0) complete
        } else {
            cp_wait0();
        }
        __syncthreads();

        const __half* sK = (const __half*)(sm + ((t & 1) ? AT_K1 : AT_K0));
        const __half* sV = (const __half*)(sm + ((t & 1) ? AT_V1 : AT_V0));

        // ---- QK (f16 accum): S' = (Q*cs2) @ K^T. 16 x 64, k = 128 ----
        unsigned sc[8][2];
        #pragma unroll
        for (int j = 0; j < 8; j++) { sc[j][0] = 0u; sc[j][1] = 0u; }

        #pragma unroll
        for (int kf = 0; kf < 8; kf++) {
            int k0 = kf * 16 + 2 * tau;
            #pragma unroll
            for (int j = 0; j < 8; j++) {
                int n = j * 8 + g;
                unsigned b0 = *(const unsigned*)&sK[n * 136 + k0];
                unsigned b1 = *(const unsigned*)&sK[n * 136 + k0 + 8];
                mma16816h(sc[j], qa[kf], b0, b1);
            }
        }

        // ---- exp + PV interleaved per 16-key chunk ----
        #pragma unroll
        for (int jj = 0; jj < 4; jj++) {
            unsigned pa[4];
            #pragma unroll
            for (int jh = 0; jh < 2; jh++) {
                int j = jj * 2 + jh;
                float2 lo = __half22float2(*(const __half2*)&sc[j][0]); // row g
                float2 hi = __half22float2(*(const __half2*)&sc[j][1]); // row g+8
                float e0 = ex2f(lo.x);
                float e1 = ex2f(lo.y);
                float e2 = ex2f(hi.x);
                float e3 = ex2f(hi.y);
                d0 += e0 + e1;
                d1 += e2 + e3;
                pa[jh * 2]     = packh2(e0 - 1.f, e1 - 1.f);
                pa[jh * 2 + 1] = packh2(e2 - 1.f, e3 - 1.f);
            }
            int k0 = jj * 16 + 2 * tau;
            #pragma unroll
            for (int j = 0; j < 16; j++) {
                int n = j * 8 + g;
                unsigned b0 = *(const unsigned*)&sV[n * 72 + k0];
                unsigned b1 = *(const unsigned*)&sV[n * 72 + k0 + 8];
                mma16816(oc[j], pa, b0, b1);
            }
        }
    }

    // ---- denominator quad-reduction (deterministic) ----
    d0 += __shfl_xor_sync(0xffffffffu, d0, 1);
    d0 += __shfl_xor_sync(0xffffffffu, d0, 2);
    d1 += __shfl_xor_sync(0xffffffffu, d1, 1);
    d1 += __shfl_xor_sync(0xffffffffu, d1, 2);
    float inv0 = 1.f / d0;
    float inv1 = 1.f / d1;

    // ---- epilogue: (p'V + colsum) / denom -> g_Oh (fp16) ----
    const float* cs = (const float*)(sm + AT_CS);
    __half* Og = g_Oh + hbase + (size_t)rb * 64 * DD;
    #pragma unroll
    for (int j = 0; j < 16; j++) {
        int c = j * 8 + 2 * tau;
        float2 csv = *(const float2*)&cs[c];
        *(unsigned*)&Og[r0 * DD + c] =
            packh2((oc[j][0] + csv.x) * inv0, (oc[j][1] + csv.y) * inv0);
        *(unsigned*)&Og[(r0 + 8) * DD + c] =
            packh2((oc[j][2] + csv.x) * inv1, (oc[j][3] + csv.y) * inv1);
    }
}

// ---------------------------------------------------------------------------
// Sum over heads (fp16 O) + 1e-8 * colsum correction -> d_out
// ---------------------------------------------------------------------------
__global__ void reduce_kernel(float* __restrict__ out) {
    int i4 = blockIdx.x * 256 + threadIdx.x;
    int base = i4 * 4;
    int c4 = base & 127;
    float4 s = make_float4(0.f, 0.f, 0.f, 0.f);
    #pragma unroll 4
    for (int h = 0; h < HH; h++) {
        const __half2* oh = (const __half2*)&g_Oh[(size_t)h * NN * DD + base];
        float2 a = __half22float2(oh[0]);
        float2 b = __half22float2(oh[1]);
        const float* cs = &g_cs[h * DD + c4];
        s.x += a.x + 1e-8f * cs[0];
        s.y += a.y + 1e-8f * cs[1];
        s.z += b.x + 1e-8f * cs[2];
        s.w += b.y + 1e-8f * cs[3];
    }
    *(float4*)&out[base] = s;
}

// ---------------------------------------------------------------------------
extern "C" void kernel_launch(void* const* d_in, const int* in_sizes, int n_in,
                              void* d_out, int out_size) {
    const float* X = (const float*)d_in[0];
    const float* W = (const float*)d_in[1];
    const float* V = (const float*)d_in[2];
    float* out = (float*)d_out;

    prep_kernel<<<2432, 256>>>(X, W, V);
    colsum_kernel<<<HH, 512>>>(V);

    cudaFuncSetAttribute(precompute_mma,
                         cudaFuncAttributeMaxDynamicSharedMemorySize, PC_TOTAL);
    precompute_mma<<<dim3(16, HH, 2), 256, PC_TOTAL>>>();

    cudaFuncSetAttribute(attn_kernel, cudaFuncAttributeMaxDynamicSharedMemorySize,
                         AT_TOTAL);
    attn_kernel<<<dim3(NN / 64, HH), 128, AT_TOTAL>>>();

    reduce_kernel<<<(NN * DD) / 1024, 256>>>(out);
}